// round 17
// baseline (speedup 1.0000x reference)
#include <cuda_runtime.h>
#include <cuda_fp16.h>
#include <cstdint>

// Problem constants
#define BN    131072
#define TT    12
#define HH    64
#define G3    192
#define CC    10
#define TOUT  12
#define NT    256            // 8 warps; warp = 16 seqs; CTA tile = 128 seqs
#define SEQ_PER_CTA 128
#define NITER 4              // seq-tiles per CTA (persistent staging)

// ---- SMEM byte offsets ----
#define OFF_A    0                 // h fp16: 128 rows x 128B, swizzled (per-warp bands)
#define OFF_WE   16384             // enc W fp16: 192 rows x 128B, swizzled
#define OFF_WD   40960             // dec W fp16
#define OFF_PKE  65536             // enc coef packs: 32 pairs x 32B
#define OFF_PKD  66560             // dec coef packs
#define OFF_BIE  67584             // enc bias packs: 4 tg x 96B (24 half2: r0-7,z0-7,n0-7)
#define OFF_BID  67968             // dec bias packs
#define OFF_L1   68352             // lin1: 64 floats + 1 bias
#define SMEM_BYTES (OFF_L1 + 65*4)
// PK pack half2 slots: [0]=war [1]=waz [2]=wan [3]=bin [4]=wbr [5]=wbz [6]=wbn [7]=pad

// device-global scratch
__device__ float g_hv[(size_t)CC * TOUT * BN * 2];   // encoder inputs (x0,x1)
__device__ float g_vals[(size_t)CC * TOUT * BN];     // decoder outputs

// ===================== helpers =====================
__device__ __forceinline__ uint32_t smem_u32_of(const void* p) {
    uint32_t a;
    asm("{ .reg .u64 t; cvta.to.shared.u64 t, %1; cvt.u32.u64 %0, t; }" : "=r"(a) : "l"(p));
    return a;
}
__device__ __forceinline__ __half2 u2h(uint32_t u) { return *(__half2*)&u; }
__device__ __forceinline__ __half2 tanh2(__half2 x) {
    uint32_t d, s = *(uint32_t*)&x;
    asm("tanh.approx.f16x2 %0, %1;" : "=r"(d) : "r"(s));
    return *(__half2*)&d;
}
// sigmoid2(x) = 0.5 + 0.5*tanh(0.5x)
__device__ __forceinline__ __half2 sigmoid2(__half2 x, __half2 h05) {
    return __hfma2(tanh2(__hmul2(x, h05)), h05, h05);
}

#define LDSM_X4(r0, r1, r2, r3, addr) \
    asm volatile("ldmatrix.sync.aligned.m8n8.x4.shared.b16 {%0,%1,%2,%3}, [%4];" \
                 : "=r"(r0), "=r"(r1), "=r"(r2), "=r"(r3) : "r"(addr))

// fp16-accumulate HMMA (validated R13/R16)
#define MMA16816H(dp, a0, a1, a2, a3, b0, b1) \
    asm volatile("mma.sync.aligned.m16n8k16.row.col.f16.f16.f16.f16 " \
                 "{%0,%1}, {%2,%3,%4,%5}, {%6,%7}, {%0,%1};" \
                 : "+r"((dp)[0]), "+r"((dp)[1]) \
                 : "r"(a0), "r"(a1), "r"(a2), "r"(a3), "r"(b0), "r"(b1))

// ===================== weight staging =====================
// W tile: fp16 swizzled (unchanged). Coefs: packed per gate-pair for LDS.128
// epilogue loads; biases packed per-tg for Dh init (bias-in-accumulator).
__device__ __forceinline__ void stage_w(
    unsigned char* smem, int tid, uint32_t wofs, uint32_t pkofs, uint32_t biofs,
    const float* __restrict__ whh, const float* __restrict__ wih, int stride,
    const float* __restrict__ bih, const float* __restrict__ bhh)
{
    for (int idx = tid; idx < G3 * HH; idx += NT) {
        int g = idx >> 6, k = idx & 63;
        __half hi = __float2half_rn(whh[idx]);
        uint32_t off = (uint32_t)g * 128u + (uint32_t)((((k >> 3) ^ (g & 7)) << 4) + (k & 7) * 2);
        *(__half*)(smem + wofs + off) = hi;
    }
    // 96 gate-pairs: q = role*32 + p, role 0:r 1:z 2:n, p = t*4+tg
    for (int q = tid; q < 96; q += NT) {
        const int role = q >> 5;
        const int p    = q & 31;
        const int t    = p >> 2;
        const int tg   = p & 3;
        const int g    = role * 64 + ((p & 31) << 1);   // first gate of pair (pair idx within role = p)
        // NOTE: gate pair within role: g2r = 2*(p) -> t=(g2r>>3)=p>>2, tg=(g2r>>1)&3=p&3 OK
        __half2 wa = __halves2half2(__float2half_rn(wih[g * stride]),
                                    __float2half_rn(wih[(g + 1) * stride]));
        __half2 wb = __halves2half2(
            __float2half_rn((stride == 2) ? wih[g * 2 + 1] : 0.0f),
            __float2half_rn((stride == 2) ? wih[(g + 1) * 2 + 1] : 0.0f));
        __half2* pk = (__half2*)(smem + pkofs + (uint32_t)p * 32u);
        pk[role]     = wa;          // slots 0,1,2 = war,waz,wan
        pk[4 + role] = wb;          // slots 4,5,6 = wbr,wbz,wbn
        if (role == 3 - 1) { /* nothing */ }
        float b0i = bih[g],     b0h = bhh[g];
        float b1i = bih[g + 1], b1h = bhh[g + 1];
        if (role < 2) {
            // r,z: bias = b_ih + b_hh -> BI pack
            __half2 bb = __halves2half2(__float2half_rn(b0i + b0h),
                                        __float2half_rn(b1i + b1h));
            *(__half2*)(smem + biofs + (uint32_t)tg * 96u + (uint32_t)(role * 8 + t) * 4u) = bb;
        } else {
            // n: b_hh -> BI pack (accumulator init); b_ih -> PK slot 3 (gx)
            __half2 bh2 = __halves2half2(__float2half_rn(b0h), __float2half_rn(b1h));
            *(__half2*)(smem + biofs + (uint32_t)tg * 96u + (uint32_t)(16 + t) * 4u) = bh2;
            pk[3] = __halves2half2(__float2half_rn(b0i), __float2half_rn(b1i));
        }
    }
}

// ===================== one GRU step (HMMA fp16-acc, packed epilogue) ============
// Dh initialized with biases (r,z: b_ih+b_hh; n: b_hh) -> no bias adds in
// epilogue. Coefs arrive via 1 (dec) / 2 (enc) LDS.128 per t.
template<bool HASX1, bool WANTV>
__device__ __forceinline__ void mma_step(
    unsigned char* smem, uint32_t smb, uint32_t wofs,
    const unsigned char* pk, const unsigned char* bi, const float* l1w,
    int warp, int group, int tg,
    int arow, int acoff, int brow, int bcoff, int sw7,
    float xa0, float xa1, float xb0, float xb1,
    float& va_out, float& vb_out)
{
    uint32_t Dh[48];
    // bias-in-accumulator init: 6x LDS.128 of this tg's bias pack, dup to rh pair
    {
        const uint4* bp = (const uint4*)bi;
        #pragma unroll
        for (int i = 0; i < 6; ++i) {
            uint4 v = bp[i];
            Dh[8 * i + 0] = v.x; Dh[8 * i + 1] = v.x;
            Dh[8 * i + 2] = v.y; Dh[8 * i + 3] = v.y;
            Dh[8 * i + 4] = v.z; Dh[8 * i + 5] = v.z;
            Dh[8 * i + 6] = v.w; Dh[8 * i + 7] = v.w;
        }
    }

    __syncwarp();

    const uint32_t a_row_b = (uint32_t)(warp * 16 + arow) * 128u;
    const uint32_t wbase = smb + wofs;

    #pragma unroll 1
    for (int kcb = 0; kcb < 4; ++kcb) {
        const int kc = kcb * 2;

        uint32_t A0, A1, A2, A3;
        uint32_t aaddr = smb + OFF_A + a_row_b + (uint32_t)(((kc + acoff) ^ sw7) << 4);
        LDSM_X4(A0, A1, A2, A3, aaddr);

        const uint32_t bsw = (uint32_t)(((kc + bcoff) ^ sw7) << 4);
        const uint32_t brb = (uint32_t)brow * 128u + bsw;
        #pragma unroll
        for (int bt = 0; bt < 12; ++bt) {
            const uint32_t brow_off = (uint32_t)(bt * 16) * 128u + brb;
            uint32_t B0, B1, B2, B3;
            LDSM_X4(B0, B1, B2, B3, wbase + brow_off);
            MMA16816H(&Dh[4 * bt],     A0, A1, A2, A3, B0, B1);
            MMA16816H(&Dh[4 * bt + 2], A0, A1, A2, A3, B2, B3);
        }
    }

    __syncwarp();

    float pa = 0.0f, pb = 0.0f;
    const __half2 h05 = __float2half2_rn(0.5f);
    const __half2 xa0h = __float2half2_rn(xa0);
    const __half2 xb0h = __float2half2_rn(xb0);
    __half2 xa1h, xb1h;
    if (HASX1) { xa1h = __float2half2_rn(xa1); xb1h = __float2half2_rn(xb1); }

    // ---- epilogue: half2 gates (bias pre-added in Dh), h update, half2 store ----
    #pragma unroll
    for (int t = 0; t < 8; ++t) {
        uint4 pka = *(const uint4*)(pk + t * 128);
        const __half2 war = u2h(pka.x), waz = u2h(pka.y),
                      wan = u2h(pka.z), bin = u2h(pka.w);
        __half2 wbr, wbz, wbn;
        if (HASX1) {
            uint4 pkb = *(const uint4*)(pk + t * 128 + 16);
            wbr = u2h(pkb.x); wbz = u2h(pkb.y); wbn = u2h(pkb.z);
        }
        float2 l1;
        if (WANTV) l1 = *(const float2*)(l1w + t * 8 + tg * 2);

        #pragma unroll
        for (int rh = 0; rh < 2; ++rh) {
            const __half2 x0h = rh ? xb0h : xa0h;
            const uint32_t off = (uint32_t)(warp * 16 + group + rh * 8) * 128u
                               + (uint32_t)(((t ^ group) << 4) + tg * 4);
            __half2 hold2 = *(__half2*)(smem + OFF_A + off);

            __half2 pr = __hfma2(war, x0h, u2h(Dh[t * 2 + rh]));
            __half2 pz = __hfma2(waz, x0h, u2h(Dh[(t + 8) * 2 + rh]));
            __half2 pn = u2h(Dh[(t + 16) * 2 + rh]);
            __half2 gx = __hfma2(wan, x0h, bin);
            if (HASX1) {
                const __half2 x1h = rh ? xb1h : xa1h;
                pr = __hfma2(wbr, x1h, pr);
                pz = __hfma2(wbz, x1h, pz);
                gx = __hfma2(wbn, x1h, gx);
            }
            __half2 rr = sigmoid2(pr, h05);
            __half2 zz = sigmoid2(pz, h05);
            __half2 nn = tanh2(__hfma2(rr, pn, gx));
            __half2 h2 = __hfma2(zz, __hsub2(hold2, nn), nn);
            *(__half2*)(smem + OFF_A + off) = h2;
            if (WANTV) {
                float2 hf = __half22float2(h2);
                float d = fmaf(hf.x, l1.x, hf.y * l1.y);
                if (rh == 0) pa += d; else pb += d;
            }
        }
    }
    if (WANTV) { va_out = pa; vb_out = pb; }
}

// ===================== main kernel =====================
__global__ void __launch_bounds__(NT, 2) krnn_mma(
    const float* __restrict__ X,
    const float* __restrict__ enc_w_ih, const float* __restrict__ enc_w_hh,
    const float* __restrict__ enc_b_ih, const float* __restrict__ enc_b_hh,
    const float* __restrict__ dec_w_ih, const float* __restrict__ dec_w_hh,
    const float* __restrict__ dec_b_ih, const float* __restrict__ dec_b_hh,
    const float* __restrict__ lin1_w,   const float* __restrict__ lin1_b)
{
    extern __shared__ unsigned char smem[];
    const int tid   = threadIdx.x;
    const int l     = tid & 31;
    const int warp  = tid >> 5;
    const int c     = (CC - 1) - blockIdx.y;          // longest-first
    const uint32_t smb = smem_u32_of(smem);

    const int group = l >> 2;
    const int tg    = l & 3;
    const int arow  = (l & 7) + ((l >> 3) & 1) * 8;
    const int acoff = (l >> 4) & 1;
    const int brow  = (l & 7) + ((l >> 4) & 1) * 8;
    const int bcoff = (l >> 3) & 1;
    const int sw7   = l & 7;

    // stage BOTH weight sets once per CTA
    stage_w(smem, tid, OFF_WE, OFF_PKE, OFF_BIE,
            enc_w_hh + c * (G3 * HH), enc_w_ih + c * (G3 * 2), 2,
            enc_b_ih + c * G3, enc_b_hh + c * G3);
    stage_w(smem, tid, OFF_WD, OFF_PKD, OFF_BID,
            dec_w_hh + c * (G3 * HH), dec_w_ih + c * G3, 1,
            dec_b_ih + c * G3, dec_b_hh + c * G3);
    {
        float* l1 = (float*)(smem + OFF_L1);
        if (tid < HH)  l1[tid] = lin1_w[c * HH + tid];
        if (tid == HH) l1[HH]  = lin1_b[c];
    }
    __syncthreads();          // the ONLY block-wide barrier

    const unsigned char* pke = smem + OFF_PKE + (uint32_t)tg * 32u;
    const unsigned char* pkd = smem + OFF_PKD + (uint32_t)tg * 32u;
    const unsigned char* bie = smem + OFF_BIE + (uint32_t)tg * 96u;
    const unsigned char* bid = smem + OFF_BID + (uint32_t)tg * 96u;
    const float* l1w = (const float*)(smem + OFF_L1);
    const float  l1b = l1w[HH];
    const int    s_enc = c + 3;
    const float2* hvc = (const float2*)g_hv + (size_t)c * TOUT * BN;
    float vdum0, vdum1;

    #pragma unroll 1
    for (int tile = 0; tile < NITER; ++tile) {
        const int seq_a = (blockIdx.x * NITER + tile) * SEQ_PER_CTA + warp * 16 + group;
        const int seq_b = seq_a + 8;

        // zero this warp's private A rows (h = 0); mma_step's syncwarp orders it
        {
            uint4 z; z.x = z.y = z.z = z.w = 0u;
            const uint32_t abase = (uint32_t)warp * 2048u;
            #pragma unroll
            for (int i = 0; i < 4; ++i)
                *(uint4*)(smem + OFF_A + abase + (uint32_t)(l * 16 + i * 512)) = z;
        }

        // ---- encoder ----
        #pragma unroll 1
        for (int st = 0; st < s_enc; ++st) {
            float2 xa = hvc[(size_t)st * BN + seq_a];
            float2 xb = hvc[(size_t)st * BN + seq_b];
            mma_step<true, false>(smem, smb, OFF_WE, pke, bie, l1w, warp, group, tg,
                                  arow, acoff, brow, bcoff, sw7,
                                  xa.x, xa.y, xb.x, xb.y, vdum0, vdum1);
        }

        // ---- decoder ----
        float va = X[(size_t)seq_a * (TT * 2) + 22];      // X[seq, t=11, f=0]
        float vb = X[(size_t)seq_b * (TT * 2) + 22];
        #pragma unroll 1
        for (int st = 0; st < TOUT; ++st) {
            float pa, pb;
            mma_step<false, true>(smem, smb, OFF_WD, pkd, bid, l1w, warp, group, tg,
                                  arow, acoff, brow, bcoff, sw7,
                                  va, 0.0f, vb, 0.0f, pa, pb);
            pa += __shfl_xor_sync(0xffffffff, pa, 1);
            pa += __shfl_xor_sync(0xffffffff, pa, 2);
            pb += __shfl_xor_sync(0xffffffff, pb, 1);
            pb += __shfl_xor_sync(0xffffffff, pb, 2);
            va = pa + l1b;
            vb = pb + l1b;
            if (tg == 0) {
                g_vals[(size_t)(c * TOUT + st) * BN + seq_a] = va;
                g_vals[(size_t)(c * TOUT + st) * BN + seq_b] = vb;
            }
        }
    }
}

// ===================== hv precompute =====================
__global__ void __launch_bounds__(256) krnn_hv(
    const float* __restrict__ X,
    const float* __restrict__ lin2_w, const float* __restrict__ lin2_b)
{
    const int seq = blockIdx.x * 256 + threadIdx.x;
    float Xl[24];
    {
        const float4* xp = (const float4*)(X + (size_t)seq * (TT * 2));
        #pragma unroll
        for (int q = 0; q < 6; ++q) {
            float4 v = xp[q];
            Xl[4*q+0] = v.x; Xl[4*q+1] = v.y; Xl[4*q+2] = v.z; Xl[4*q+3] = v.w;
        }
    }
    float2* hvp = (float2*)g_hv;
    for (int c = 0; c < CC; ++c) {
        const int s = c + 3;
        for (int st = 0; st < s; ++st) {
            float b = lin2_b[c * 12 + st];
            float x0 = b, x1 = b;
            #pragma unroll
            for (int t = 0; t < TT; ++t) {
                float w = lin2_w[c * 144 + st * 12 + t];
                x0 = fmaf(Xl[2 * t],     w, x0);
                x1 = fmaf(Xl[2 * t + 1], w, x1);
            }
            hvp[(size_t)(c * TOUT + st) * BN + seq] = make_float2(x0, x1);
        }
    }
}

// ===================== final combine =====================
__global__ void __launch_bounds__(256) krnn_combine(
    const float* __restrict__ X,
    const float* __restrict__ embed1,
    float* __restrict__ out)
{
    const int seq = blockIdx.x * 256 + threadIdx.x;

    float q[TT];
    #pragma unroll
    for (int t = 0; t < TT; ++t) q[t] = X[(size_t)seq * (TT * 2) + t * 2];

    float wq[TOUT];
    #pragma unroll
    for (int o = 0; o < TOUT; ++o) {
        float a = 0.0f;
        #pragma unroll
        for (int t = 0; t < TT; ++t) a = fmaf(q[t], embed1[t * TOUT + o], a);
        wq[o] = a;
    }

    float ov[TOUT * CC];
    #pragma unroll
    for (int cc = 0; cc < CC; ++cc)
        #pragma unroll
        for (int o = 0; o < TOUT; ++o)
            ov[o * CC + cc] = g_vals[((size_t)cc * TOUT + o) * BN + seq];

    float wc[CC];
    #pragma unroll
    for (int cc = 0; cc < CC; ++cc) {
        float a = 0.0f;
        #pragma unroll
        for (int o = 0; o < TOUT; ++o) a = fmaf(wq[o], ov[o * CC + cc], a);
        wc[cc] = a;
    }

    float m = wc[0];
    #pragma unroll
    for (int cc = 1; cc < CC; ++cc) m = fmaxf(m, wc[cc]);
    float e[CC]; float ssum = 0.0f;
    #pragma unroll
    for (int cc = 0; cc < CC; ++cc) { e[cc] = expf(wc[cc] - m); ssum += e[cc]; }
    float inv = 1.0f / ssum;

    #pragma unroll
    for (int o = 0; o < TOUT; ++o) {
        float a = 0.0f;
        #pragma unroll
        for (int cc = 0; cc < CC; ++cc) a = fmaf(ov[o * CC + cc], e[cc], a);
        out[(size_t)seq * TOUT + o] = a * inv;
    }
}

extern "C" void kernel_launch(void* const* d_in, const int* in_sizes, int n_in,
                              void* d_out, int out_size)
{
    const float* X        = (const float*)d_in[1];
    const float* enc_w_ih = (const float*)d_in[2];
    const float* enc_w_hh = (const float*)d_in[3];
    const float* enc_b_ih = (const float*)d_in[4];
    const float* enc_b_hh = (const float*)d_in[5];
    const float* dec_w_ih = (const float*)d_in[6];
    const float* dec_w_hh = (const float*)d_in[7];
    const float* dec_b_ih = (const float*)d_in[8];
    const float* dec_b_hh = (const float*)d_in[9];
    const float* lin1_w   = (const float*)d_in[10];
    const float* lin1_b   = (const float*)d_in[11];
    const float* lin2_w   = (const float*)d_in[12];
    const float* lin2_b   = (const float*)d_in[13];
    const float* embed1   = (const float*)d_in[14];

    cudaFuncSetAttribute(krnn_mma, cudaFuncAttributeMaxDynamicSharedMemorySize, SMEM_BYTES);

    krnn_hv<<<BN / 256, 256>>>(X, lin2_w, lin2_b);

    dim3 grid(BN / (SEQ_PER_CTA * NITER), CC);
    krnn_mma<<<grid, NT, SMEM_BYTES>>>(
        X, enc_w_ih, enc_w_hh, enc_b_ih, enc_b_hh,
        dec_w_ih, dec_w_hh, dec_b_ih, dec_b_hh,
        lin1_w, lin1_b);

    krnn_combine<<<BN / 256, 256>>>(X, embed1, (float*)d_out);
}